// round 10
// baseline (speedup 1.0000x reference)
#include <cuda_runtime.h>
#include <math.h>

#define NB 32
#define NT 36
#define NN 10000
#define NF 3
#define NH 10
#define NR 20
#define PRED_ELEMS (NB * NH * NN)   // 3,200,000
#define NPB 1024                    // nodes per block (4x wider contiguous run)
#define NPT 4                       // nodes per thread
#define THREADS 256
#define NBLK_X ((NN + NPB - 1) / NPB)   // 10
#define NBLOCKS (NBLK_X * NB)           // 320
#define T3 3                        // t-steps per load batch (12 loads in flight)

// ---------------- device scratch (zero-initialized at module load; ----------------
// ---------------- last block restores zeros every launch -> replay-safe) ----------
__device__ float g_rsum[NB * NR];
__device__ float g_rcnt[NB * NR];
__device__ int   g_nan_count;
__device__ int   g_nan_list[NB * NN];
__device__ unsigned int g_done;

// ---------------- K1: everything in one kernel ----------------
// grid (10, 32), block 256; thread handles 4 nodes (n0+tid+{0,256,512,768}).
// Per (block, t) the contiguous DRAM footprint is 12 KB (vs 3 KB before) and
// only 320 regions are concurrently active (vs 1280) -> better HBM row
// locality, which R6-R9 identified as the limiter (DRAM stuck at 58% with all
// SM-side knobs ineffective).
__global__ void __launch_bounds__(THREADS, 6) k1_fused(
    const float* __restrict__ seq, const int* __restrict__ cid32,
    float* __restrict__ out) {
    const int b = blockIdx.y;
    const int n0 = blockIdx.x * NPB;
    const int tid = threadIdx.x;
    const int nbase = n0 + tid;

    __shared__ float s_rsum[NR];
    __shared__ float s_rcnt[NR];
    if (tid < NR) { s_rsum[tid] = 0.0f; s_rcnt[tid] = 0.0f; }

    // int64-vs-int32 probe for cluster_id (if int64, all odd words are 0;
    // values 0..19 -> misfire P = 20^-64).
    int bad = 0;
    if (tid < 64) bad = (cid32[2 * tid + 1] != 0);
    const int is64 = (__syncthreads_or(bad) == 0);   // also covers smem init sync

    // one base pointer; all 144 loads use immediate offsets from it
    const float* base = seq + (size_t)b * (NT * NN * NF) + (size_t)nbase * NF;
    const bool valid[NPT] = { nbase < NN, nbase + 256 < NN,
                              nbase + 512 < NN, nbase + 768 < NN };

    float s[NPT] = {0.f, 0.f, 0.f, 0.f};
    float c[NPT] = {0.f, 0.f, 0.f, 0.f};
#pragma unroll
    for (int tb = 0; tb < NT / T3; tb++) {
        float x[T3][NPT];
#pragma unroll
        for (int j = 0; j < T3; j++) {
#pragma unroll
            for (int k = 0; k < NPT; k++) {
                // clamp invalid lanes to a safe in-bounds address; masked below
                const int off = valid[k] ? ((tb * T3 + j) * (NN * NF) + k * 256 * NF) : 0;
                x[j][k] = __ldg(base + off);
            }
        }
#pragma unroll
        for (int j = 0; j < T3; j++) {
#pragma unroll
            for (int k = 0; k < NPT; k++) {
                if (valid[k] && x[j][k] == x[j][k]) { s[k] += x[j][k]; c[k] += 1.0f; }
            }
        }
    }

#pragma unroll
    for (int k = 0; k < NPT; k++) {
        if (!valid[k]) continue;
        const int n = nbase + k * 256;
        const float tm = s[k] / c[k];       // 0/0 -> NaN when node all-NaN

        // broadcast the 10 horizon copies (coalesced 128B per warp per h)
#pragma unroll
        for (int h = 0; h < NH; h++) {
            out[(size_t)(b * NH + h) * NN + n] = tm;
        }

        if (tm == tm) {
            const int r = is64 ? cid32[2 * n] : cid32[n];
            atomicAdd(&s_rsum[r], tm);
            atomicAdd(&s_rcnt[r], 1.0f);
        } else {
            int idx = atomicAdd(&g_nan_count, 1);
            g_nan_list[idx] = b * NN + n;
        }
    }
    __syncthreads();
    if (tid < NR) {
        atomicAdd(&g_rsum[b * NR + tid], s_rsum[tid]);
    } else if (tid < 2 * NR) {
        const int r = tid - NR;
        atomicAdd(&g_rcnt[b * NR + r], s_rcnt[r]);
    }

    // ---------------- last-block finalization ----------------
    __threadfence();
    __shared__ unsigned int s_ticket;
    __syncthreads();
    if (tid == 0) s_ticket = atomicAdd(&g_done, 1u);
    __syncthreads();
    if (s_ticket != NBLOCKS - 1) return;

    // v0/v1 -> g1 (valid-node sum/count); v2/v3 -> g2 (mean of valid regional)
    float v0 = 0.f, v1 = 0.f, v2 = 0.f, v3 = 0.f;
    for (int i = tid; i < NB * NR; i += THREADS) {
        const float rs = g_rsum[i];
        const float rc = g_rcnt[i];
        const float reg = rs / rc;
        v0 += rs; v1 += rc;
        if (reg == reg) { v2 += reg; v3 += 1.0f; }
    }
#pragma unroll
    for (int o = 16; o > 0; o >>= 1) {
        v0 += __shfl_down_sync(0xFFFFFFFFu, v0, o);
        v1 += __shfl_down_sync(0xFFFFFFFFu, v1, o);
        v2 += __shfl_down_sync(0xFFFFFFFFu, v2, o);
        v3 += __shfl_down_sync(0xFFFFFFFFu, v3, o);
    }
    __shared__ float sw[8][4];
    const int w = tid >> 5, l = tid & 31;
    if (l == 0) { sw[w][0] = v0; sw[w][1] = v1; sw[w][2] = v2; sw[w][3] = v3; }
    __syncthreads();
    __shared__ float s_g1, s_g2;
    if (w == 0) {
        float a0 = (l < 8) ? sw[l][0] : 0.0f;
        float a1 = (l < 8) ? sw[l][1] : 0.0f;
        float a2 = (l < 8) ? sw[l][2] : 0.0f;
        float a3 = (l < 8) ? sw[l][3] : 0.0f;
#pragma unroll
        for (int o = 4; o > 0; o >>= 1) {
            a0 += __shfl_down_sync(0xFFFFFFFFu, a0, o);
            a1 += __shfl_down_sync(0xFFFFFFFFu, a1, o);
            a2 += __shfl_down_sync(0xFFFFFFFFu, a2, o);
            a3 += __shfl_down_sync(0xFFFFFFFFu, a3, o);
        }
        if (l == 0) { s_g1 = a0 / a1; s_g2 = a2 / a3; }
    }
    __syncthreads();
    const float g1 = s_g1, g2 = s_g2;

    // regional output (NaN regions -> g2), then re-zero accumulators
    float* outR = out + PRED_ELEMS;
    for (int i = tid; i < NB * NR; i += THREADS) {
        const int bb = i / NR, rr = i % NR;
        const float reg = g_rsum[i] / g_rcnt[i];
        const float val = (reg == reg) ? reg : g2;
#pragma unroll
        for (int h = 0; h < NH; h++) {
            outR[(bb * NH + h) * NR + rr] = val;
        }
        g_rsum[i] = 0.0f;
        g_rcnt[i] = 0.0f;
    }

    // fix the (statistically nonexistent) all-NaN pred cells with g1
    const int cnt = g_nan_count;
    for (int idx = tid; idx < cnt; idx += THREADS) {
        const int bn = g_nan_list[idx];
        const int bb = bn / NN, nn = bn % NN;
#pragma unroll
        for (int h = 0; h < NH; h++) {
            out[(size_t)(bb * NH + h) * NN + nn] = g1;
        }
    }
    if (tid == 0) {
        g_nan_count = 0;
        g_done = 0;
    }
}

// ---------------- launcher ----------------
extern "C" void kernel_launch(void* const* d_in, const int* in_sizes, int n_in,
                              void* d_out, int out_size) {
    const float* seq = (const float*)d_in[0];
    const int* cid = (const int*)d_in[1];   // int32 or int64 -- probed in-kernel
    float* out = (float*)d_out;

    dim3 grid(NBLK_X, NB);
    k1_fused<<<grid, THREADS>>>(seq, cid, out);
}

// round 12
// speedup vs baseline: 1.2987x; 1.2987x over previous
#include <cuda_runtime.h>
#include <math.h>

#define NB 32
#define NT 36
#define NN 10000
#define NF 3
#define NH 10
#define NR 20
#define PRED_ELEMS (NB * NH * NN)   // 3,200,000
#define NBLK_X ((NN + 255) / 256)   // 40 blocks per batch
#define NBLOCKS (NBLK_X * NB)       // 1280

// ---------------- device scratch (zero-initialized at module load; ----------------
// ---------------- finalizers restore zeros every launch -> replay-safe) -----------
__device__ float g_rsum[NB * NR];
__device__ float g_rcnt[NB * NR];
__device__ float g_pb[NB][4];            // per-batch partials: sum,cnt,regsum,regcnt
__device__ int   g_nan_count;            // all-NaN (b,n) cells
__device__ int   g_nan_list[NB * NN];
__device__ int   g_badreg_count;         // all-NaN (b,r) regions
__device__ int   g_badreg[NB * NR];
__device__ unsigned int g_doneB[NB];     // per-batch tickets (32 distinct addrs)
__device__ unsigned int g_done;          // global ticket (only 32 arrivals)

// ---------------- K1: stream + hierarchical finalize ----------------
// grid (40, 32), block 256; one thread per (b, n). Scalar stride-12B loads
// (warp covers 384 contiguous B per t -> optimal L1 wavefronts).
__global__ void __launch_bounds__(256) k1_fused(
    const float* __restrict__ seq, const int* __restrict__ cid32,
    float* __restrict__ out) {
    const int b = blockIdx.y;
    const int n = blockIdx.x * blockDim.x + threadIdx.x;
    const int tid = threadIdx.x;

    __shared__ float s_rsum[NR];
    __shared__ float s_rcnt[NR];
    if (tid < NR) { s_rsum[tid] = 0.0f; s_rcnt[tid] = 0.0f; }

    // int64-vs-int32 probe for cluster_id (if int64, all odd words are 0;
    // values 0..19 -> misfire P = 20^-64).
    int bad = 0;
    if (tid < 64) bad = (cid32[2 * tid + 1] != 0);
    const int is64 = (__syncthreads_or(bad) == 0);   // also covers smem init sync

    if (n < NN) {
        const float* base = seq + (size_t)b * (NT * NN * NF) + (size_t)n * NF;
        float s = 0.0f, c = 0.0f;
#pragma unroll
        for (int t = 0; t < NT; t++) {
            float x = __ldg(base + (size_t)t * (NN * NF));
            if (x == x) { s += x; c += 1.0f; }
        }
        const float tm = s / c;             // 0/0 -> NaN when node all-NaN

        // broadcast the 10 horizon copies (store pipe idle under load latency)
#pragma unroll
        for (int h = 0; h < NH; h++) {
            out[(size_t)(b * NH + h) * NN + n] = tm;
        }

        if (tm == tm) {
            const int r = is64 ? cid32[2 * n] : cid32[n];
            atomicAdd(&s_rsum[r], tm);
            atomicAdd(&s_rcnt[r], 1.0f);
        } else {
            int idx = atomicAdd(&g_nan_count, 1);
            g_nan_list[idx] = b * NN + n;
        }
    }
    __syncthreads();
    if (tid < NR) {
        atomicAdd(&g_rsum[b * NR + tid], s_rsum[tid]);
    } else if (tid < 2 * NR) {
        const int r = tid - NR;
        atomicAdd(&g_rcnt[b * NR + r], s_rcnt[r]);
    }

    // ---------------- per-batch ticket (32 distinct addresses, 40 ops each) -------
    __threadfence();
    __shared__ unsigned int s_t;
    __syncthreads();
    if (tid == 0) s_t = atomicAdd(&g_doneB[b], 1u);
    __syncthreads();
    if (s_t != NBLK_X - 1) return;

    // ======== per-batch finalize (runs overlapped across 32 staggered blocks) =====
    if (tid == 0) g_doneB[b] = 0;           // reset own ticket for next replay

    float rs = 0.f, rc = 0.f, reg = 0.f;
    bool rv = false;
    if (tid < NR) {
        rs = g_rsum[b * NR + tid];
        rc = g_rcnt[b * NR + tid];
        reg = rs / rc;                      // NaN if region empty for this batch
        rv = (reg == reg);
        float* outR = out + PRED_ELEMS;
        if (rv) {
#pragma unroll
            for (int h = 0; h < NH; h++) {
                outR[(b * NH + h) * NR + tid] = reg;
            }
        } else {
            int idx = atomicAdd(&g_badreg_count, 1);
            g_badreg[idx] = b * NR + tid;
        }
        g_rsum[b * NR + tid] = 0.0f;        // reset for next replay
        g_rcnt[b * NR + tid] = 0.0f;
    }
    // warp 0 reduces this batch's partials (lanes >= NR contribute zeros)
    if (tid < 32) {
        float v0 = rs, v1 = rc;
        float v2 = rv ? reg : 0.0f, v3 = rv ? 1.0f : 0.0f;
#pragma unroll
        for (int o = 16; o > 0; o >>= 1) {
            v0 += __shfl_down_sync(0xFFFFFFFFu, v0, o);
            v1 += __shfl_down_sync(0xFFFFFFFFu, v1, o);
            v2 += __shfl_down_sync(0xFFFFFFFFu, v2, o);
            v3 += __shfl_down_sync(0xFFFFFFFFu, v3, o);
        }
        if (tid == 0) {
            g_pb[b][0] = v0; g_pb[b][1] = v1;
            g_pb[b][2] = v2; g_pb[b][3] = v3;
        }
    }

    // ---------------- global ticket (only 32 arrivals total) ----------------
    __threadfence();
    __syncthreads();
    if (tid == 0) s_t = atomicAdd(&g_done, 1u);
    __syncthreads();
    if (s_t != NB - 1) return;

    // ======== global finalize: tiny (32x4 reduce + statistically-empty fixups) ====
    __shared__ float s_g1, s_g2;
    if (tid < 32) {
        float v0 = g_pb[tid][0], v1 = g_pb[tid][1];
        float v2 = g_pb[tid][2], v3 = g_pb[tid][3];
#pragma unroll
        for (int o = 16; o > 0; o >>= 1) {
            v0 += __shfl_down_sync(0xFFFFFFFFu, v0, o);
            v1 += __shfl_down_sync(0xFFFFFFFFu, v1, o);
            v2 += __shfl_down_sync(0xFFFFFFFFu, v2, o);
            v3 += __shfl_down_sync(0xFFFFFFFFu, v3, o);
        }
        if (tid == 0) { s_g1 = v0 / v1; s_g2 = v2 / v3; }
    }
    __syncthreads();
    const float g1 = s_g1, g2 = s_g2;

    // all-NaN regions -> g2 (normally zero iterations)
    const int bc = g_badreg_count;
    float* outR = out + PRED_ELEMS;
    for (int idx = tid; idx < bc; idx += 256) {
        const int br = g_badreg[idx];
        const int bb = br / NR, rr = br % NR;
#pragma unroll
        for (int h = 0; h < NH; h++) {
            outR[(bb * NH + h) * NR + rr] = g2;
        }
    }
    // all-NaN pred cells -> g1 (normally zero iterations)
    const int cnt = g_nan_count;
    for (int idx = tid; idx < cnt; idx += 256) {
        const int bn = g_nan_list[idx];
        const int bb = bn / NN, nn = bn % NN;
#pragma unroll
        for (int h = 0; h < NH; h++) {
            out[(size_t)(bb * NH + h) * NN + nn] = g1;
        }
    }
    if (tid == 0) {
        g_nan_count = 0;
        g_badreg_count = 0;
        g_done = 0;
    }
}

// ---------------- launcher ----------------
extern "C" void kernel_launch(void* const* d_in, const int* in_sizes, int n_in,
                              void* d_out, int out_size) {
    const float* seq = (const float*)d_in[0];
    const int* cid = (const int*)d_in[1];   // int32 or int64 -- probed in-kernel
    float* out = (float*)d_out;

    dim3 grid(NBLK_X, NB);
    k1_fused<<<grid, 256>>>(seq, cid, out);
}